// round 1
// baseline (speedup 1.0000x reference)
#include <cuda_runtime.h>
#include <cuda_bf16.h>
#include <math.h>

// ---------------- problem constants ----------------
#define T_TOK  2048
#define HID    4096
#define NH     32
#define DN     128   // qk_nope
#define DR     64    // qk_rope
#define DH     192   // qk_head
#define DV     128   // v_head
#define QL     1536  // q_lora
#define KVL    512   // kv_lora

// ---------------- device scratch (no allocations allowed) ----------------
__device__ float g_qa   [(size_t)T_TOK * QL];                 // 12.6 MB  (q lora, rmsnorm in place)
__device__ float g_q    [(size_t)T_TOK * NH * DH];            // 50.3 MB  (q, rope in place)
__device__ float g_kva  [(size_t)T_TOK * (KVL + DR)];         // 4.7 MB   (c_kv | k_pe)
__device__ float g_kv   [(size_t)T_TOK * NH * (DN + DV)];     // 67 MB    (k_nope | v per head)
__device__ float g_kfull[(size_t)T_TOK * NH * DH];            // 50.3 MB
__device__ float g_s    [(size_t)NH * T_TOK * T_TOK];         // 536 MB   (scores/probs)
__device__ float g_attn [(size_t)T_TOK * NH * DV];            // 33.6 MB

// ---------------- generic fp32 GEMM ----------------
// C[m,n] = alpha * sum_k A[m,k] * (TRANSB ? B[n,k] : B[k,n])
// Requirements: M % 128 == 0, K % 16 == 0, N % 8 == 0 (N guarded).
// BM=BN=128, BK=16, 256 threads, 8x8 micro-tile.
template <bool TRANSB>
__global__ __launch_bounds__(256)
void sgemm_kernel(const float* __restrict__ A, const float* __restrict__ B,
                  float* __restrict__ C,
                  int M, int N, int K, int lda, int ldb, int ldc,
                  long long sA, long long sB, long long sC, float alpha)
{
    const int BM = 128, BN = 128, BK = 16;
    __shared__ __align__(16) float As[BK][BM];
    __shared__ __align__(16) float Bs[BK][BN];

    const int z = blockIdx.z;
    A += (size_t)z * sA;
    B += (size_t)z * sB;
    C += (size_t)z * sC;

    const int m0 = blockIdx.y * BM;
    const int n0 = blockIdx.x * BN;
    const int tid = threadIdx.x;
    const int ty = tid >> 4;       // 0..15 (m)
    const int tx = tid & 15;       // 0..15 (n)

    // A-load mapping: 128 rows x 16 k, 8 floats per thread (same row, 8 consecutive k)
    const int arow = tid >> 1;           // 0..127
    const int akb  = (tid & 1) * 8;      // 0 or 8

    float acc[8][8];
#pragma unroll
    for (int i = 0; i < 8; i++)
#pragma unroll
        for (int j = 0; j < 8; j++) acc[i][j] = 0.0f;

    for (int k0 = 0; k0 < K; k0 += BK) {
        // ---- load A tile (always in-bounds: M%128==0, K%16==0) ----
        {
            const float* ap = &A[(size_t)(m0 + arow) * lda + k0 + akb];
            float4 a0 = *(const float4*)(ap);
            float4 a1 = *(const float4*)(ap + 4);
            As[akb + 0][arow] = a0.x; As[akb + 1][arow] = a0.y;
            As[akb + 2][arow] = a0.z; As[akb + 3][arow] = a0.w;
            As[akb + 4][arow] = a1.x; As[akb + 5][arow] = a1.y;
            As[akb + 6][arow] = a1.z; As[akb + 7][arow] = a1.w;
        }
        // ---- load B tile ----
        if (!TRANSB) {
            const int bk = tid >> 4;          // 0..15
            const int bn = (tid & 15) * 8;    // 0..120
            float4 b0 = make_float4(0.f, 0.f, 0.f, 0.f), b1 = b0;
            if (n0 + bn < N) {                // N%8==0 -> all-or-nothing
                const float* bp = &B[(size_t)(k0 + bk) * ldb + n0 + bn];
                b0 = *(const float4*)(bp);
                b1 = *(const float4*)(bp + 4);
            }
            *(float4*)&Bs[bk][bn]     = b0;
            *(float4*)&Bs[bk][bn + 4] = b1;
        } else {
            const int brow = tid >> 1;        // n index 0..127
            const int bkb  = (tid & 1) * 8;
            float4 b0 = make_float4(0.f, 0.f, 0.f, 0.f), b1 = b0;
            if (n0 + brow < N) {
                const float* bp = &B[(size_t)(n0 + brow) * ldb + k0 + bkb];
                b0 = *(const float4*)(bp);
                b1 = *(const float4*)(bp + 4);
            }
            Bs[bkb + 0][brow] = b0.x; Bs[bkb + 1][brow] = b0.y;
            Bs[bkb + 2][brow] = b0.z; Bs[bkb + 3][brow] = b0.w;
            Bs[bkb + 4][brow] = b1.x; Bs[bkb + 5][brow] = b1.y;
            Bs[bkb + 6][brow] = b1.z; Bs[bkb + 7][brow] = b1.w;
        }
        __syncthreads();

#pragma unroll
        for (int kk = 0; kk < BK; kk++) {
            float a[8], b[8];
            float4 t0 = *(const float4*)&As[kk][ty * 8];
            float4 t1 = *(const float4*)&As[kk][ty * 8 + 4];
            a[0]=t0.x; a[1]=t0.y; a[2]=t0.z; a[3]=t0.w;
            a[4]=t1.x; a[5]=t1.y; a[6]=t1.z; a[7]=t1.w;
            float4 u0 = *(const float4*)&Bs[kk][tx * 8];
            float4 u1 = *(const float4*)&Bs[kk][tx * 8 + 4];
            b[0]=u0.x; b[1]=u0.y; b[2]=u0.z; b[3]=u0.w;
            b[4]=u1.x; b[5]=u1.y; b[6]=u1.z; b[7]=u1.w;
#pragma unroll
            for (int i = 0; i < 8; i++)
#pragma unroll
                for (int j = 0; j < 8; j++)
                    acc[i][j] = fmaf(a[i], b[j], acc[i][j]);
        }
        __syncthreads();
    }

    // ---- store C (guard on N only) ----
    const int nbase = n0 + tx * 8;
    if (nbase < N) {
#pragma unroll
        for (int i = 0; i < 8; i++) {
            const int m = m0 + ty * 8 + i;
            float4 c0, c1;
            c0.x = alpha * acc[i][0]; c0.y = alpha * acc[i][1];
            c0.z = alpha * acc[i][2]; c0.w = alpha * acc[i][3];
            c1.x = alpha * acc[i][4]; c1.y = alpha * acc[i][5];
            c1.z = alpha * acc[i][6]; c1.w = alpha * acc[i][7];
            *(float4*)&C[(size_t)m * ldc + nbase]     = c0;
            *(float4*)&C[(size_t)m * ldc + nbase + 4] = c1;
        }
    }
}

// ---------------- rmsnorm (in place, first `w` columns of each row) ----------------
__global__ void rmsnorm_kernel(float* __restrict__ x, const float* __restrict__ g,
                               int rowstride, int w)
{
    const int row = blockIdx.x;
    float* p = x + (size_t)row * rowstride;
    __shared__ float red[256];
    float s = 0.0f;
    for (int c = threadIdx.x; c < w; c += 256) {
        float v = p[c];
        s += v * v;
    }
    red[threadIdx.x] = s;
    __syncthreads();
    for (int o = 128; o > 0; o >>= 1) {
        if (threadIdx.x < o) red[threadIdx.x] += red[threadIdx.x + o];
        __syncthreads();
    }
    const float r = rsqrtf(red[0] / (float)w + 1e-6f);
    for (int c = threadIdx.x; c < w; c += 256)
        p[c] = p[c] * r * g[c];
}

// ---------------- interleaved RoPE (64-dim section, in place) ----------------
__global__ void rope_kernel(float* __restrict__ base, const int* __restrict__ positions,
                            int rowstride, int headstride, int offset)
{
    const int t = blockIdx.x;
    const int h = blockIdx.y;
    const int i = threadIdx.x;  // 0..31
    float* p = base + (size_t)t * rowstride + h * headstride + offset;
    const float pos = (float)positions[t];
    const float inv = powf(10000.0f, -(float)(2 * i) / 64.0f);
    float sn, cs;
    sincosf(pos * inv, &sn, &cs);
    const float x1 = p[2 * i];
    const float x2 = p[2 * i + 1];
    p[2 * i]     = x1 * cs - x2 * sn;
    p[2 * i + 1] = x1 * sn + x2 * cs;
}

// ---------------- build k_full = [k_nope | broadcast k_pe] ----------------
__global__ void kfull_kernel()
{
    const int t = blockIdx.x;
    const int h = blockIdx.y;
    const int d = threadIdx.x;  // 0..191
    float v;
    if (d < DN) v = g_kv[(size_t)t * (NH * (DN + DV)) + h * (DN + DV) + d];
    else        v = g_kva[(size_t)t * (KVL + DR) + KVL + (d - DN)];
    g_kfull[(size_t)t * (NH * DH) + h * DH + d] = v;
}

// ---------------- causal softmax over scores rows (in place) ----------------
__global__ void softmax_kernel(const int* __restrict__ positions)
{
    const int q = blockIdx.x;
    const int h = blockIdx.y;
    float* row = g_s + ((size_t)h * T_TOK + q) * T_TOK;
    const int pq = positions[q];
    __shared__ float red[256];
    const int tid = threadIdx.x;

    float m = -INFINITY;
    for (int j = tid; j < T_TOK; j += 256)
        if (positions[j] <= pq) m = fmaxf(m, row[j]);
    red[tid] = m;
    __syncthreads();
    for (int o = 128; o > 0; o >>= 1) {
        if (tid < o) red[tid] = fmaxf(red[tid], red[tid + o]);
        __syncthreads();
    }
    m = red[0];
    __syncthreads();

    float s = 0.0f;
    for (int j = tid; j < T_TOK; j += 256) {
        float v = 0.0f;
        if (positions[j] <= pq) {
            v = expf(row[j] - m);
            s += v;
        }
        row[j] = v;
    }
    red[tid] = s;
    __syncthreads();
    for (int o = 128; o > 0; o >>= 1) {
        if (tid < o) red[tid] += red[tid + o];
        __syncthreads();
    }
    const float inv = 1.0f / red[0];
    for (int j = tid; j < T_TOK; j += 256)
        row[j] *= inv;
}

// ---------------- launcher ----------------
extern "C" void kernel_launch(void* const* d_in, const int* in_sizes, int n_in,
                              void* d_out, int out_size)
{
    const int*   positions = (const int*)  d_in[0];
    const float* hidden    = (const float*)d_in[1];
    const float* wq_a      = (const float*)d_in[2];
    const float* gq        = (const float*)d_in[3];
    const float* wq_b      = (const float*)d_in[4];
    const float* wkv_a     = (const float*)d_in[5];
    const float* gkv       = (const float*)d_in[6];
    const float* wkv_b     = (const float*)d_in[7];
    const float* wo        = (const float*)d_in[8];
    float* out = (float*)d_out;

    float *qa, *q, *kva, *kv, *kfull, *s, *attn;
    cudaGetSymbolAddress((void**)&qa,    g_qa);
    cudaGetSymbolAddress((void**)&q,     g_q);
    cudaGetSymbolAddress((void**)&kva,   g_kva);
    cudaGetSymbolAddress((void**)&kv,    g_kv);
    cudaGetSymbolAddress((void**)&kfull, g_kfull);
    cudaGetSymbolAddress((void**)&s,     g_s);
    cudaGetSymbolAddress((void**)&attn,  g_attn);

    const float scale = 1.0f / sqrtf((float)DH);
    const dim3 blk(256);

    // 1. qa = hidden @ wq_a          [2048,1536]
    sgemm_kernel<false><<<dim3(QL / 128, T_TOK / 128, 1), blk>>>(
        hidden, wq_a, qa, T_TOK, QL, HID, HID, QL, QL, 0, 0, 0, 1.0f);

    // 2. rmsnorm(qa) * gq  (in place)
    rmsnorm_kernel<<<T_TOK, blk>>>(qa, gq, QL, QL);

    // 3. q = qln @ wq_b              [2048,6144]
    sgemm_kernel<false><<<dim3(NH * DH / 128, T_TOK / 128, 1), blk>>>(
        qa, wq_b, q, T_TOK, NH * DH, QL, QL, NH * DH, NH * DH, 0, 0, 0, 1.0f);

    // 4. kva = hidden @ wkv_a        [2048,576]
    sgemm_kernel<false><<<dim3((KVL + DR + 127) / 128, T_TOK / 128, 1), blk>>>(
        hidden, wkv_a, kva, T_TOK, KVL + DR, HID, HID, KVL + DR, KVL + DR, 0, 0, 0, 1.0f);

    // 5. rmsnorm first 512 cols of kva with gkv (in place; k_pe untouched)
    rmsnorm_kernel<<<T_TOK, blk>>>(kva, gkv, KVL + DR, KVL);

    // 6. kv = ckv_ln @ wkv_b         [2048,8192]
    sgemm_kernel<false><<<dim3(NH * (DN + DV) / 128, T_TOK / 128, 1), blk>>>(
        kva, wkv_b, kv, T_TOK, NH * (DN + DV), KVL, KVL + DR, NH * (DN + DV),
        NH * (DN + DV), 0, 0, 0, 1.0f);

    // 7. rope q_pe (per head, in place)
    rope_kernel<<<dim3(T_TOK, NH), 32>>>(q, positions, NH * DH, DH, DN);

    // 8. rope k_pe (in place in kva)
    rope_kernel<<<dim3(T_TOK, 1), 32>>>(kva, positions, KVL + DR, 0, KVL);

    // 9. build k_full
    kfull_kernel<<<dim3(T_TOK, NH), DH>>>();

    // 10. scores[h] = scale * q[h] @ kfull[h]^T     (batched over heads)
    sgemm_kernel<true><<<dim3(T_TOK / 128, T_TOK / 128, NH), blk>>>(
        q, kfull, s, T_TOK, T_TOK, DH, NH * DH, NH * DH, T_TOK,
        (long long)DH, (long long)DH, (long long)T_TOK * T_TOK, scale);

    // 11. causal softmax (in place)
    softmax_kernel<<<dim3(T_TOK, NH), blk>>>(positions);

    // 12. attn[h] = probs[h] @ v[h]                 (batched over heads)
    sgemm_kernel<false><<<dim3(1, T_TOK / 128, NH), blk>>>(
        s, kv + DN, attn, T_TOK, DV, T_TOK, T_TOK, NH * (DN + DV), NH * DV,
        (long long)T_TOK * T_TOK, (long long)(DN + DV), (long long)DV, 1.0f);

    // 13. out = attn @ wo            [2048,4096]
    sgemm_kernel<false><<<dim3(HID / 128, T_TOK / 128, 1), blk>>>(
        attn, wo, out, T_TOK, HID, NH * DV, NH * DV, HID, HID, 0, 0, 0, 1.0f);
}

// round 3
// speedup vs baseline: 2.4658x; 2.4658x over previous
#include <cuda_runtime.h>
#include <cuda_bf16.h>
#include <math.h>
#include <stdint.h>

// ---------------- problem constants ----------------
#define T_TOK  2048
#define HID    4096
#define NH     32
#define DN     128   // qk_nope
#define DR     64    // qk_rope
#define DH     192   // qk_head
#define DV     128   // v_head
#define QL     1536  // q_lora
#define KVL    512   // kv_lora

// ---------------- device scratch ----------------
__device__ float g_qa    [(size_t)T_TOK * QL];
__device__ float g_q     [(size_t)T_TOK * NH * DH];
__device__ float g_kva   [(size_t)T_TOK * (KVL + DR)];
__device__ float g_kv    [(size_t)T_TOK * NH * (DN + DV)];
__device__ float g_kfull [(size_t)T_TOK * NH * DH];
__device__ float g_s     [(size_t)NH * T_TOK * T_TOK];
__device__ float g_attn  [(size_t)T_TOK * NH * DV];
__device__ float g_rowsum[(size_t)NH * T_TOK];

// ---------------- helpers ----------------
__device__ __forceinline__ uint32_t round_tf32_bits(float x) {
    float y;
    asm("cvt.rna.tf32.f32 %0, %1;" : "=f"(y) : "f"(x));
    return __float_as_uint(y);
}

__device__ __forceinline__ void mma_tf32(float* c, const uint32_t* a, const uint32_t* b) {
    asm volatile(
        "mma.sync.aligned.m16n8k8.row.col.f32.tf32.tf32.f32 "
        "{%0,%1,%2,%3}, {%4,%5,%6,%7}, {%8,%9}, {%0,%1,%2,%3};"
        : "+f"(c[0]), "+f"(c[1]), "+f"(c[2]), "+f"(c[3])
        : "r"(a[0]), "r"(a[1]), "r"(a[2]), "r"(a[3]), "r"(b[0]), "r"(b[1]));
}

// ---------------- tensor-core tf32 GEMM (mma.sync) ----------------
// C[m,n] = alpha * sum_k A[m,k] * (TRANSB ? B[n,k] : B[k,n])
// BM=BN=128, BK=32, 256 threads (8 warps: 4m x 2n), warp tile 32x64.
// Requirements: M%128==0, K%32==0, N%8==0 (N guarded per 8-col tile).
// SKIPN: skip tiles with n0 > m0+127 (causal scores).
// CLAMPK: clamp K to m0+128 (causal PV).
template <bool TRANSB, bool SKIPN, bool CLAMPK>
__global__ __launch_bounds__(256, 1)
void tmma_gemm(const float* __restrict__ A, const float* __restrict__ B,
               float* __restrict__ C,
               int M, int N, int K, int lda, int ldb, int ldc,
               long long sA, long long sB, long long sC, float alpha)
{
    // A: [128][36] row-major (m,k)  -> fragment reads conflict-free (bank = 4g+tig)
    // B (NT): [32][136] (k,n)       -> fragment reads conflict-free (bank = 8k+n)
    // B (T):  [128][36] (n,k)       -> same pattern as A
    __shared__ __align__(16) uint32_t As[128][36];
    __shared__ __align__(16) uint32_t Bs[4608];   // max(32*136, 128*36) = 4608

    const int tid = threadIdx.x;
    const int wid = tid >> 5;
    const int lane = tid & 31;
    const int g   = lane >> 2;   // groupID
    const int tig = lane & 3;    // thread in group

    const int wm = (wid >> 1) * 32;   // warp m offset (0,32,64,96)
    const int wn = (wid & 1) * 64;    // warp n offset (0,64)

    const int z  = blockIdx.z;
    const int m0 = blockIdx.y * 128;
    const int n0 = blockIdx.x * 128;

    if (SKIPN && n0 > m0 + 127) return;

    A += (size_t)z * sA;
    B += (size_t)z * sB;
    C += (size_t)z * sC;

    int Keff = K;
    if (CLAMPK) Keff = min(K, m0 + 128);
    const int nkt = Keff >> 5;

    float acc[2][8][4];
#pragma unroll
    for (int mt = 0; mt < 2; mt++)
#pragma unroll
        for (int nt = 0; nt < 8; nt++)
#pragma unroll
            for (int r = 0; r < 4; r++) acc[mt][nt][r] = 0.0f;

    for (int kt = 0; kt < nkt; kt++) {
        const int k0 = kt << 5;

        // ---- fill A tile: 128 rows x 32 k (1024 float4) ----
#pragma unroll
        for (int i = 0; i < 4; i++) {
            const int t   = i * 256 + tid;
            const int row = t >> 3;
            const int kq  = (t & 7) * 4;
            float4 v = *(const float4*)(A + (size_t)(m0 + row) * lda + k0 + kq);
            uint4 u;
            u.x = round_tf32_bits(v.x); u.y = round_tf32_bits(v.y);
            u.z = round_tf32_bits(v.z); u.w = round_tf32_bits(v.w);
            *(uint4*)&As[row][kq] = u;
        }

        // ---- fill B tile ----
        if (TRANSB) {
            // rows are n (128), cols are k (32)
#pragma unroll
            for (int i = 0; i < 4; i++) {
                const int t   = i * 256 + tid;
                const int row = t >> 3;
                const int kq  = (t & 7) * 4;
                float4 v = make_float4(0.f, 0.f, 0.f, 0.f);
                if (n0 + row < N)
                    v = *(const float4*)(B + (size_t)(n0 + row) * ldb + k0 + kq);
                uint4 u;
                u.x = round_tf32_bits(v.x); u.y = round_tf32_bits(v.y);
                u.z = round_tf32_bits(v.z); u.w = round_tf32_bits(v.w);
                *(uint4*)&Bs[row * 36 + kq] = u;
            }
        } else {
            // rows are k (32), cols are n (128)
#pragma unroll
            for (int i = 0; i < 4; i++) {
                const int t  = i * 256 + tid;
                const int k  = t >> 5;
                const int nq = (t & 31) * 4;
                float4 v = make_float4(0.f, 0.f, 0.f, 0.f);
                if (n0 + nq < N)
                    v = *(const float4*)(B + (size_t)(k0 + k) * ldb + n0 + nq);
                uint4 u;
                u.x = round_tf32_bits(v.x); u.y = round_tf32_bits(v.y);
                u.z = round_tf32_bits(v.z); u.w = round_tf32_bits(v.w);
                *(uint4*)&Bs[k * 136 + nq] = u;
            }
        }
        __syncthreads();

        // ---- compute: 4 k-steps of m16n8k8 ----
#pragma unroll
        for (int ks = 0; ks < 4; ks++) {
            const int kk = ks * 8;
            uint32_t af[2][4];
#pragma unroll
            for (int mt = 0; mt < 2; mt++) {
                const int rb = wm + mt * 16 + g;
                af[mt][0] = As[rb][kk + tig];
                af[mt][1] = As[rb + 8][kk + tig];
                af[mt][2] = As[rb][kk + tig + 4];
                af[mt][3] = As[rb + 8][kk + tig + 4];
            }
            uint32_t bf[8][2];
#pragma unroll
            for (int nt = 0; nt < 8; nt++) {
                const int nb = wn + nt * 8 + g;
                if (TRANSB) {
                    bf[nt][0] = Bs[nb * 36 + kk + tig];
                    bf[nt][1] = Bs[nb * 36 + kk + tig + 4];
                } else {
                    bf[nt][0] = Bs[(kk + tig) * 136 + nb];
                    bf[nt][1] = Bs[(kk + tig + 4) * 136 + nb];
                }
            }
#pragma unroll
            for (int mt = 0; mt < 2; mt++)
#pragma unroll
                for (int nt = 0; nt < 8; nt++)
                    mma_tf32(acc[mt][nt], af[mt], bf[nt]);
        }
        __syncthreads();
    }

    // ---- epilogue: direct C store (float2 per mma row) ----
#pragma unroll
    for (int mt = 0; mt < 2; mt++) {
#pragma unroll
        for (int nt = 0; nt < 8; nt++) {
            const int col = n0 + wn + nt * 8 + 2 * tig;
            if (col < N) {
                const int r0 = m0 + wm + mt * 16 + g;
                float2 v0 = make_float2(alpha * acc[mt][nt][0], alpha * acc[mt][nt][1]);
                float2 v1 = make_float2(alpha * acc[mt][nt][2], alpha * acc[mt][nt][3]);
                *(float2*)&C[(size_t)r0 * ldc + col] = v0;
                *(float2*)&C[(size_t)(r0 + 8) * ldc + col] = v1;
            }
        }
    }
}

// ---------------- rmsnorm ----------------
__global__ void rmsnorm_kernel(float* __restrict__ x, const float* __restrict__ g,
                               int rowstride, int w)
{
    const int row = blockIdx.x;
    float* p = x + (size_t)row * rowstride;
    __shared__ float red[256];
    float s = 0.0f;
    for (int c = threadIdx.x; c < w; c += 256) { float v = p[c]; s += v * v; }
    red[threadIdx.x] = s;
    __syncthreads();
    for (int o = 128; o > 0; o >>= 1) {
        if (threadIdx.x < o) red[threadIdx.x] += red[threadIdx.x + o];
        __syncthreads();
    }
    const float r = rsqrtf(red[0] / (float)w + 1e-6f);
    for (int c = threadIdx.x; c < w; c += 256)
        p[c] = p[c] * r * g[c];
}

// ---------------- interleaved RoPE ----------------
__global__ void rope_kernel(float* __restrict__ base, const int* __restrict__ positions,
                            int rowstride, int headstride, int offset)
{
    const int t = blockIdx.x;
    const int h = blockIdx.y;
    const int i = threadIdx.x;  // 0..31
    float* p = base + (size_t)t * rowstride + h * headstride + offset;
    const float pos = (float)positions[t];
    const float inv = powf(10000.0f, -(float)(2 * i) / 64.0f);
    float sn, cs;
    sincosf(pos * inv, &sn, &cs);
    const float x1 = p[2 * i];
    const float x2 = p[2 * i + 1];
    p[2 * i]     = x1 * cs - x2 * sn;
    p[2 * i + 1] = x1 * sn + x2 * cs;
}

// ---------------- build k_full ----------------
__global__ void kfull_kernel()
{
    const int t = blockIdx.x;
    const int h = blockIdx.y;
    const int d = threadIdx.x;
    float v;
    if (d < DN) v = g_kv[(size_t)t * (NH * (DN + DV)) + h * (DN + DV) + d];
    else        v = g_kva[(size_t)t * (KVL + DR) + KVL + (d - DN)];
    g_kfull[(size_t)t * (NH * DH) + h * DH + d] = v;
}

// ---------------- causal softmax: unnormalized exp + row sums ----------------
__global__ void softmax_kernel(const int* __restrict__ positions)
{
    const int q = blockIdx.x;
    const int h = blockIdx.y;
    float* row = g_s + ((size_t)h * T_TOK + q) * T_TOK;
    const int pq = positions[q];
    __shared__ float red[256];
    const int tid = threadIdx.x;

    float m = -INFINITY;
    for (int j = tid; j < T_TOK; j += 256)
        if (positions[j] <= pq) m = fmaxf(m, row[j]);
    red[tid] = m;
    __syncthreads();
    for (int o = 128; o > 0; o >>= 1) {
        if (tid < o) red[tid] = fmaxf(red[tid], red[tid + o]);
        __syncthreads();
    }
    m = red[0];
    __syncthreads();

    float s = 0.0f;
    for (int j = tid; j < T_TOK; j += 256) {
        float v = 0.0f;
        if (positions[j] <= pq) { v = __expf(row[j] - m); s += v; }
        row[j] = v;
    }
    red[tid] = s;
    __syncthreads();
    for (int o = 128; o > 0; o >>= 1) {
        if (tid < o) red[tid] += red[tid + o];
        __syncthreads();
    }
    if (tid == 0) g_rowsum[(size_t)h * T_TOK + q] = red[0];
}

// ---------------- normalize attn rows by softmax sums ----------------
__global__ void attn_norm_kernel()
{
    const int t = blockIdx.x;
    float* p = g_attn + (size_t)t * (NH * DV);
    for (int c = threadIdx.x; c < NH * DV; c += 256) {
        const int h = c >> 7;
        p[c] *= 1.0f / g_rowsum[(size_t)h * T_TOK + t];
    }
}

// ---------------- launcher ----------------
extern "C" void kernel_launch(void* const* d_in, const int* in_sizes, int n_in,
                              void* d_out, int out_size)
{
    const int*   positions = (const int*)  d_in[0];
    const float* hidden    = (const float*)d_in[1];
    const float* wq_a      = (const float*)d_in[2];
    const float* gq        = (const float*)d_in[3];
    const float* wq_b      = (const float*)d_in[4];
    const float* wkv_a     = (const float*)d_in[5];
    const float* gkv       = (const float*)d_in[6];
    const float* wkv_b     = (const float*)d_in[7];
    const float* wo        = (const float*)d_in[8];
    float* out = (float*)d_out;

    float *qa, *q, *kva, *kv, *kfull, *s, *attn;
    cudaGetSymbolAddress((void**)&qa,    g_qa);
    cudaGetSymbolAddress((void**)&q,     g_q);
    cudaGetSymbolAddress((void**)&kva,   g_kva);
    cudaGetSymbolAddress((void**)&kv,    g_kv);
    cudaGetSymbolAddress((void**)&kfull, g_kfull);
    cudaGetSymbolAddress((void**)&s,     g_s);
    cudaGetSymbolAddress((void**)&attn,  g_attn);

    const float scale = 1.0f / sqrtf((float)DH);
    const dim3 blk(256);

    // 1. qa = hidden @ wq_a          [2048,1536] K=4096
    tmma_gemm<false,false,false><<<dim3(QL/128, T_TOK/128, 1), blk>>>(
        hidden, wq_a, qa, T_TOK, QL, HID, HID, QL, QL, 0, 0, 0, 1.0f);

    // 2. rmsnorm(qa)
    rmsnorm_kernel<<<T_TOK, 256>>>(qa, gq, QL, QL);

    // 3. q = qln @ wq_b              [2048,6144] K=1536
    tmma_gemm<false,false,false><<<dim3(NH*DH/128, T_TOK/128, 1), blk>>>(
        qa, wq_b, q, T_TOK, NH*DH, QL, QL, NH*DH, NH*DH, 0, 0, 0, 1.0f);

    // 4. kva = hidden @ wkv_a        [2048,576] K=4096
    tmma_gemm<false,false,false><<<dim3((KVL+DR+127)/128, T_TOK/128, 1), blk>>>(
        hidden, wkv_a, kva, T_TOK, KVL+DR, HID, HID, KVL+DR, KVL+DR, 0, 0, 0, 1.0f);

    // 5. rmsnorm first 512 cols of kva
    rmsnorm_kernel<<<T_TOK, 256>>>(kva, gkv, KVL+DR, KVL);

    // 6. kv = ckv_ln @ wkv_b         [2048,8192] K=512
    tmma_gemm<false,false,false><<<dim3(NH*(DN+DV)/128, T_TOK/128, 1), blk>>>(
        kva, wkv_b, kv, T_TOK, NH*(DN+DV), KVL, KVL+DR, NH*(DN+DV), NH*(DN+DV),
        0, 0, 0, 1.0f);

    // 7. rope q_pe
    rope_kernel<<<dim3(T_TOK, NH), 32>>>(q, positions, NH*DH, DH, DN);

    // 8. rope k_pe
    rope_kernel<<<dim3(T_TOK, 1), 32>>>(kva, positions, KVL+DR, 0, KVL);

    // 9. k_full
    kfull_kernel<<<dim3(T_TOK, NH), DH>>>();

    // 10. scores[h] = scale * q[h] @ kfull[h]^T   (causal tile skip)
    tmma_gemm<true,true,false><<<dim3(T_TOK/128, T_TOK/128, NH), blk>>>(
        q, kfull, s, T_TOK, T_TOK, DH, NH*DH, NH*DH, T_TOK,
        (long long)DH, (long long)DH, (long long)T_TOK*T_TOK, scale);

    // 11. causal softmax (unnormalized exp + row sums)
    softmax_kernel<<<dim3(T_TOK, NH), 256>>>(positions);

    // 12. attn[h] = exp_probs[h] @ v[h]           (causal K clamp)
    tmma_gemm<false,false,true><<<dim3(1, T_TOK/128, NH), blk>>>(
        s, kv + DN, attn, T_TOK, DV, T_TOK, T_TOK, NH*(DN+DV), NH*DV,
        (long long)T_TOK*T_TOK, (long long)(DN+DV), (long long)DV, 1.0f);

    // 12b. normalize attn by row sums
    attn_norm_kernel<<<T_TOK, 256>>>();

    // 13. out = attn @ wo            [2048,4096]
    tmma_gemm<false,false,false><<<dim3(HID/128, T_TOK/128, 1), blk>>>(
        attn, wo, out, T_TOK, HID, NH*DV, NH*DV, HID, HID, 0, 0, 0, 1.0f);
}

// round 4
// speedup vs baseline: 3.3639x; 1.3642x over previous
#include <cuda_runtime.h>
#include <cuda_bf16.h>
#include <math.h>
#include <stdint.h>

// ---------------- problem constants ----------------
#define T_TOK  2048
#define HID    4096
#define NH     32
#define DN     128   // qk_nope
#define DR     64    // qk_rope
#define DH     192   // qk_head
#define DV     128   // v_head
#define QL     1536  // q_lora
#define KVL    512   // kv_lora

// ---------------- device scratch ----------------
__device__ float g_qa    [(size_t)T_TOK * QL];
__device__ float g_q     [(size_t)T_TOK * NH * DH];
__device__ float g_kva   [(size_t)T_TOK * (KVL + DR)];
__device__ float g_kv    [(size_t)T_TOK * NH * (DN + DV)];
__device__ float g_kfull [(size_t)T_TOK * NH * DH];
__device__ float g_s     [(size_t)NH * T_TOK * T_TOK];
__device__ float g_attn  [(size_t)T_TOK * NH * DV];
__device__ float g_rowsum[(size_t)NH * T_TOK];

// ---------------- helpers ----------------
__device__ __forceinline__ uint32_t round_tf32_bits(float x) {
    float y;
    asm("cvt.rna.tf32.f32 %0, %1;" : "=f"(y) : "f"(x));
    return __float_as_uint(y);
}

__device__ __forceinline__ void mma_tf32(float* c, const uint32_t* a, const uint32_t* b) {
    asm volatile(
        "mma.sync.aligned.m16n8k8.row.col.f32.tf32.tf32.f32 "
        "{%0,%1,%2,%3}, {%4,%5,%6,%7}, {%8,%9}, {%0,%1,%2,%3};"
        : "+f"(c[0]), "+f"(c[1]), "+f"(c[2]), "+f"(c[3])
        : "r"(a[0]), "r"(a[1]), "r"(a[2]), "r"(a[3]), "r"(b[0]), "r"(b[1]));
}

#define CP_ASYNC16(dst_u32, src_ptr, sz) \
    asm volatile("cp.async.cg.shared.global [%0], [%1], 16, %2;" \
        :: "r"(dst_u32), "l"(src_ptr), "r"(sz))
#define CP_COMMIT() asm volatile("cp.async.commit_group;" ::: "memory")
#define CP_WAIT1()  asm volatile("cp.async.wait_group 1;" ::: "memory")
#define CP_WAIT0()  asm volatile("cp.async.wait_group 0;" ::: "memory")

// ---------------- tensor-core tf32 GEMM (mma.sync + cp.async pipeline) ----------------
// C[m,n] = alpha * sum_k A[m,k] * (TRANSB ? B[n,k] : B[k,n])
// BM=BN=128, BK=64, 256 threads (8 warps: 4m x 2n), warp tile 32x64, 2-stage cp.async.
// Requirements: M%128==0, K%64==0 (after clamp), N%8==0.
// SKIPN: skip tiles with n0 > m0+127 (causal scores).
// CLAMPK: clamp K to m0+128 (causal PV).
//
// SMEM (floats): A stage = [128][68] = 8704 words; B stage = 8704 words
//   (T layout [128][68], NT layout [64][136]).  2 stages each => 34816 words = 136 KB.
#define STG_WORDS 8704
#define GEMM_SMEM_BYTES (4 * STG_WORDS * 4)

template <bool TRANSB, bool SKIPN, bool CLAMPK>
__global__ __launch_bounds__(256)
void tmma_gemm(const float* __restrict__ A, const float* __restrict__ B,
               float* __restrict__ C,
               int M, int N, int K, int lda, int ldb, int ldc,
               long long sA, long long sB, long long sC, float alpha)
{
    extern __shared__ float smf[];
    float* Abuf = smf;                   // 2 x 8704
    float* Bbuf = smf + 2 * STG_WORDS;   // 2 x 8704

    const int tid  = threadIdx.x;
    const int wid  = tid >> 5;
    const int lane = tid & 31;
    const int g    = lane >> 2;
    const int tig  = lane & 3;

    const int wm = (wid >> 1) * 32;
    const int wn = (wid & 1) * 64;

    const int z  = blockIdx.z;
    const int m0 = blockIdx.y * 128;
    const int n0 = blockIdx.x * 128;

    if (SKIPN && n0 > m0 + 127) return;

    A += (size_t)z * sA;
    B += (size_t)z * sB;
    C += (size_t)z * sC;

    int Keff = K;
    if (CLAMPK) Keff = min(K, m0 + 128);
    const int nkt = Keff >> 6;

    const uint32_t a_sm = (uint32_t)__cvta_generic_to_shared(Abuf);
    const uint32_t b_sm = (uint32_t)__cvta_generic_to_shared(Bbuf);

    // ---- async loaders ----
    auto load_tile = [&](int kt, int st) {
        const int k0 = kt << 6;
        const uint32_t asb = a_sm + (uint32_t)st * STG_WORDS * 4;
        const uint32_t bsb = b_sm + (uint32_t)st * STG_WORDS * 4;
        // A: 128 rows x 64 k  (16 float4 per row)
#pragma unroll
        for (int i = 0; i < 8; i++) {
            const int idx = i * 256 + tid;
            const int row = idx >> 4;
            const int c4  = (idx & 15) * 4;
            const uint32_t dst = asb + (uint32_t)(row * 68 + c4) * 4;
            const float* src = A + (size_t)(m0 + row) * lda + k0 + c4;
            CP_ASYNC16(dst, src, 16);
        }
        if (TRANSB) {
            // B: 128 rows(n) x 64 k
#pragma unroll
            for (int i = 0; i < 8; i++) {
                const int idx = i * 256 + tid;
                const int row = idx >> 4;
                const int c4  = (idx & 15) * 4;
                const bool in = (n0 + row < N);
                const uint32_t dst = bsb + (uint32_t)(row * 68 + c4) * 4;
                const float* src = in ? (B + (size_t)(n0 + row) * ldb + k0 + c4) : B;
                CP_ASYNC16(dst, src, in ? 16 : 0);
            }
        } else {
            // B: 64 rows(k) x 128 cols(n)
#pragma unroll
            for (int i = 0; i < 8; i++) {
                const int idx = i * 256 + tid;
                const int row = idx >> 5;
                const int c4  = (idx & 31) * 4;
                const bool in = (n0 + c4 < N);
                const uint32_t dst = bsb + (uint32_t)(row * 136 + c4) * 4;
                const float* src = in ? (B + (size_t)(k0 + row) * ldb + n0 + c4) : B;
                CP_ASYNC16(dst, src, in ? 16 : 0);
            }
        }
    };

    float acc[2][8][4];
#pragma unroll
    for (int mt = 0; mt < 2; mt++)
#pragma unroll
        for (int nt = 0; nt < 8; nt++)
#pragma unroll
            for (int r = 0; r < 4; r++) acc[mt][nt][r] = 0.0f;

    load_tile(0, 0);
    CP_COMMIT();

    for (int kt = 0; kt < nkt; kt++) {
        if (kt + 1 < nkt) {
            load_tile(kt + 1, (kt + 1) & 1);
            CP_COMMIT();
            CP_WAIT1();
        } else {
            CP_WAIT0();
        }
        __syncthreads();

        const float* Ast = Abuf + (kt & 1) * STG_WORDS;
        const float* Bst = Bbuf + (kt & 1) * STG_WORDS;

#pragma unroll
        for (int ks = 0; ks < 8; ks++) {
            const int kk = ks * 8;
            uint32_t af[2][4];
#pragma unroll
            for (int mt = 0; mt < 2; mt++) {
                const int rb = wm + mt * 16 + g;
                af[mt][0] = round_tf32_bits(Ast[rb * 68 + kk + tig]);
                af[mt][1] = round_tf32_bits(Ast[(rb + 8) * 68 + kk + tig]);
                af[mt][2] = round_tf32_bits(Ast[rb * 68 + kk + tig + 4]);
                af[mt][3] = round_tf32_bits(Ast[(rb + 8) * 68 + kk + tig + 4]);
            }
            uint32_t bf[8][2];
#pragma unroll
            for (int nt = 0; nt < 8; nt++) {
                const int nb = wn + nt * 8 + g;
                if (TRANSB) {
                    bf[nt][0] = round_tf32_bits(Bst[nb * 68 + kk + tig]);
                    bf[nt][1] = round_tf32_bits(Bst[nb * 68 + kk + tig + 4]);
                } else {
                    bf[nt][0] = round_tf32_bits(Bst[(kk + tig) * 136 + nb]);
                    bf[nt][1] = round_tf32_bits(Bst[(kk + tig + 4) * 136 + nb]);
                }
            }
#pragma unroll
            for (int mt = 0; mt < 2; mt++)
#pragma unroll
                for (int nt = 0; nt < 8; nt++)
                    mma_tf32(acc[mt][nt], af[mt], bf[nt]);
        }
        __syncthreads();
    }

    // ---- epilogue ----
#pragma unroll
    for (int mt = 0; mt < 2; mt++) {
#pragma unroll
        for (int nt = 0; nt < 8; nt++) {
            const int col = n0 + wn + nt * 8 + 2 * tig;
            if (col < N) {
                const int r0 = m0 + wm + mt * 16 + g;
                float2 v0 = make_float2(alpha * acc[mt][nt][0], alpha * acc[mt][nt][1]);
                float2 v1 = make_float2(alpha * acc[mt][nt][2], alpha * acc[mt][nt][3]);
                *(float2*)&C[(size_t)r0 * ldc + col] = v0;
                *(float2*)&C[(size_t)(r0 + 8) * ldc + col] = v1;
            }
        }
    }
}

// ---------------- rmsnorm ----------------
__global__ void rmsnorm_kernel(float* __restrict__ x, const float* __restrict__ g,
                               int rowstride, int w)
{
    const int row = blockIdx.x;
    float* p = x + (size_t)row * rowstride;
    __shared__ float red[256];
    float s = 0.0f;
    for (int c = threadIdx.x; c < w; c += 256) { float v = p[c]; s += v * v; }
    red[threadIdx.x] = s;
    __syncthreads();
    for (int o = 128; o > 0; o >>= 1) {
        if (threadIdx.x < o) red[threadIdx.x] += red[threadIdx.x + o];
        __syncthreads();
    }
    const float r = rsqrtf(red[0] / (float)w + 1e-6f);
    for (int c = threadIdx.x; c < w; c += 256)
        p[c] = p[c] * r * g[c];
}

// ---------------- interleaved RoPE ----------------
__global__ void rope_kernel(float* __restrict__ base, const int* __restrict__ positions,
                            int rowstride, int headstride, int offset)
{
    const int t = blockIdx.x;
    const int h = blockIdx.y;
    const int i = threadIdx.x;  // 0..31
    float* p = base + (size_t)t * rowstride + h * headstride + offset;
    const float pos = (float)positions[t];
    const float inv = powf(10000.0f, -(float)(2 * i) / 64.0f);
    float sn, cs;
    sincosf(pos * inv, &sn, &cs);
    const float x1 = p[2 * i];
    const float x2 = p[2 * i + 1];
    p[2 * i]     = x1 * cs - x2 * sn;
    p[2 * i + 1] = x1 * sn + x2 * cs;
}

// ---------------- build k_full ----------------
__global__ void kfull_kernel()
{
    const int t = blockIdx.x;
    const int h = blockIdx.y;
    const int d = threadIdx.x;
    float v;
    if (d < DN) v = g_kv[(size_t)t * (NH * (DN + DV)) + h * (DN + DV) + d];
    else        v = g_kva[(size_t)t * (KVL + DR) + KVL + (d - DN)];
    g_kfull[(size_t)t * (NH * DH) + h * DH + d] = v;
}

// ---------------- causal softmax: unnormalized exp + row sums ----------------
// Only touches j < jmax = next 128-boundary above q (PV reads exactly that range).
__global__ void softmax_kernel(const int* __restrict__ positions)
{
    const int q = blockIdx.x;
    const int h = blockIdx.y;
    float* row = g_s + ((size_t)h * T_TOK + q) * T_TOK;
    const int pq = positions[q];
    const int jmax = ((q >> 7) + 1) << 7;
    __shared__ float red[256];
    const int tid = threadIdx.x;

    float m = -INFINITY;
    for (int j = tid; j < jmax; j += 256)
        if (positions[j] <= pq) m = fmaxf(m, row[j]);
    red[tid] = m;
    __syncthreads();
    for (int o = 128; o > 0; o >>= 1) {
        if (tid < o) red[tid] = fmaxf(red[tid], red[tid + o]);
        __syncthreads();
    }
    m = red[0];
    __syncthreads();

    float s = 0.0f;
    for (int j = tid; j < jmax; j += 256) {
        float v = 0.0f;
        if (positions[j] <= pq) { v = __expf(row[j] - m); s += v; }
        row[j] = v;
    }
    red[tid] = s;
    __syncthreads();
    for (int o = 128; o > 0; o >>= 1) {
        if (tid < o) red[tid] += red[tid + o];
        __syncthreads();
    }
    if (tid == 0) g_rowsum[(size_t)h * T_TOK + q] = red[0];
}

// ---------------- normalize attn rows by softmax sums ----------------
__global__ void attn_norm_kernel()
{
    const int t = blockIdx.x;
    float* p = g_attn + (size_t)t * (NH * DV);
    for (int c = threadIdx.x; c < NH * DV; c += 256) {
        const int h = c >> 7;
        p[c] *= 1.0f / g_rowsum[(size_t)h * T_TOK + t];
    }
}

// ---------------- launcher ----------------
extern "C" void kernel_launch(void* const* d_in, const int* in_sizes, int n_in,
                              void* d_out, int out_size)
{
    const int*   positions = (const int*)  d_in[0];
    const float* hidden    = (const float*)d_in[1];
    const float* wq_a      = (const float*)d_in[2];
    const float* gq        = (const float*)d_in[3];
    const float* wq_b      = (const float*)d_in[4];
    const float* wkv_a     = (const float*)d_in[5];
    const float* gkv       = (const float*)d_in[6];
    const float* wkv_b     = (const float*)d_in[7];
    const float* wo        = (const float*)d_in[8];
    float* out = (float*)d_out;

    float *qa, *q, *kva, *kv, *kfull, *s, *attn;
    cudaGetSymbolAddress((void**)&qa,    g_qa);
    cudaGetSymbolAddress((void**)&q,     g_q);
    cudaGetSymbolAddress((void**)&kva,   g_kva);
    cudaGetSymbolAddress((void**)&kv,    g_kv);
    cudaGetSymbolAddress((void**)&kfull, g_kfull);
    cudaGetSymbolAddress((void**)&s,     g_s);
    cudaGetSymbolAddress((void**)&attn,  g_attn);

    static bool attr_done = false;
    if (!attr_done) {
        cudaFuncSetAttribute(tmma_gemm<false,false,false>,
            cudaFuncAttributeMaxDynamicSharedMemorySize, GEMM_SMEM_BYTES);
        cudaFuncSetAttribute(tmma_gemm<true,true,false>,
            cudaFuncAttributeMaxDynamicSharedMemorySize, GEMM_SMEM_BYTES);
        cudaFuncSetAttribute(tmma_gemm<false,false,true>,
            cudaFuncAttributeMaxDynamicSharedMemorySize, GEMM_SMEM_BYTES);
        attr_done = true;
    }

    const float scale = 1.0f / sqrtf((float)DH);
    const dim3 blk(256);
    const int  shm = GEMM_SMEM_BYTES;

    // 1. qa = hidden @ wq_a          [2048,1536] K=4096
    tmma_gemm<false,false,false><<<dim3(QL/128, T_TOK/128, 1), blk, shm>>>(
        hidden, wq_a, qa, T_TOK, QL, HID, HID, QL, QL, 0, 0, 0, 1.0f);

    // 2. rmsnorm(qa)
    rmsnorm_kernel<<<T_TOK, 256>>>(qa, gq, QL, QL);

    // 3. q = qln @ wq_b              [2048,6144] K=1536
    tmma_gemm<false,false,false><<<dim3(NH*DH/128, T_TOK/128, 1), blk, shm>>>(
        qa, wq_b, q, T_TOK, NH*DH, QL, QL, NH*DH, NH*DH, 0, 0, 0, 1.0f);

    // 4. kva = hidden @ wkv_a        [2048,576] K=4096
    tmma_gemm<false,false,false><<<dim3((KVL+DR+127)/128, T_TOK/128, 1), blk, shm>>>(
        hidden, wkv_a, kva, T_TOK, KVL+DR, HID, HID, KVL+DR, KVL+DR, 0, 0, 0, 1.0f);

    // 5. rmsnorm first 512 cols of kva
    rmsnorm_kernel<<<T_TOK, 256>>>(kva, gkv, KVL+DR, KVL);

    // 6. kv = ckv_ln @ wkv_b         [2048,8192] K=512
    tmma_gemm<false,false,false><<<dim3(NH*(DN+DV)/128, T_TOK/128, 1), blk, shm>>>(
        kva, wkv_b, kv, T_TOK, NH*(DN+DV), KVL, KVL+DR, NH*(DN+DV), NH*(DN+DV),
        0, 0, 0, 1.0f);

    // 7. rope q_pe
    rope_kernel<<<dim3(T_TOK, NH), 32>>>(q, positions, NH*DH, DH, DN);

    // 8. rope k_pe
    rope_kernel<<<dim3(T_TOK, 1), 32>>>(kva, positions, KVL+DR, 0, KVL);

    // 9. k_full
    kfull_kernel<<<dim3(T_TOK, NH), DH>>>();

    // 10. scores[h] = scale * q[h] @ kfull[h]^T   (causal tile skip)
    tmma_gemm<true,true,false><<<dim3(T_TOK/128, T_TOK/128, NH), blk, shm>>>(
        q, kfull, s, T_TOK, T_TOK, DH, NH*DH, NH*DH, T_TOK,
        (long long)DH, (long long)DH, (long long)T_TOK*T_TOK, scale);

    // 11. causal softmax (unnormalized exp + row sums, tile-bounded)
    softmax_kernel<<<dim3(T_TOK, NH), 256>>>(positions);

    // 12. attn[h] = exp_probs[h] @ v[h]           (causal K clamp)
    tmma_gemm<false,false,true><<<dim3(1, T_TOK/128, NH), blk, shm>>>(
        s, kv + DN, attn, T_TOK, DV, T_TOK, T_TOK, NH*(DN+DV), NH*DV,
        (long long)T_TOK*T_TOK, (long long)(DN+DV), (long long)DV, 1.0f);

    // 12b. normalize attn by row sums
    attn_norm_kernel<<<T_TOK, 256>>>();

    // 13. out = attn @ wo            [2048,4096]
    tmma_gemm<false,false,false><<<dim3(HID/128, T_TOK/128, 1), blk, shm>>>(
        attn, wo, out, T_TOK, HID, NH*DV, NH*DV, HID, HID, 0, 0, 0, 1.0f);
}

// round 5
// speedup vs baseline: 3.5830x; 1.0651x over previous
#include <cuda_runtime.h>
#include <cuda_bf16.h>
#include <math.h>
#include <stdint.h>

// ---------------- problem constants ----------------
#define T_TOK  2048
#define HID    4096
#define NH     32
#define DN     128   // qk_nope
#define DR     64    // qk_rope
#define DH     192   // qk_head
#define DV     128   // v_head
#define QL     1536  // q_lora
#define KVL    512   // kv_lora

// ---------------- device scratch ----------------
__device__ float g_qa    [(size_t)T_TOK * QL];
__device__ float g_q     [(size_t)T_TOK * NH * DH];
__device__ float g_kva   [(size_t)T_TOK * (KVL + DR)];
__device__ float g_kv    [(size_t)T_TOK * NH * (DN + DV)];
__device__ float g_kfull [(size_t)T_TOK * NH * DH];
__device__ float g_s     [(size_t)NH * T_TOK * T_TOK];
__device__ float g_attn  [(size_t)T_TOK * NH * DV];
__device__ float g_rowsum[(size_t)NH * T_TOK];
// tf32-rounded copies of raw inputs
__device__ float g_hidr  [(size_t)T_TOK * HID];
__device__ float g_wqa   [(size_t)HID * QL];
__device__ float g_wqb   [(size_t)QL * NH * DH];
__device__ float g_wkva  [(size_t)HID * (KVL + DR)];
__device__ float g_wkvb  [(size_t)KVL * NH * (DN + DV)];
__device__ float g_wo    [(size_t)NH * DV * HID];

// ---------------- helpers ----------------
__device__ __forceinline__ float round_tf32(float x) {
    float y;
    asm("cvt.rna.tf32.f32 %0, %1;" : "=f"(y) : "f"(x));
    return y;
}

__device__ __forceinline__ void mma_tf32(float* c, const uint32_t* a, const uint32_t* b) {
    asm volatile(
        "mma.sync.aligned.m16n8k8.row.col.f32.tf32.tf32.f32 "
        "{%0,%1,%2,%3}, {%4,%5,%6,%7}, {%8,%9}, {%0,%1,%2,%3};"
        : "+f"(c[0]), "+f"(c[1]), "+f"(c[2]), "+f"(c[3])
        : "r"(a[0]), "r"(a[1]), "r"(a[2]), "r"(a[3]), "r"(b[0]), "r"(b[1]));
}

#define CP_ASYNC16(dst_u32, src_ptr, sz) \
    asm volatile("cp.async.cg.shared.global [%0], [%1], 16, %2;" \
        :: "r"(dst_u32), "l"(src_ptr), "r"(sz))
#define CP_COMMIT() asm volatile("cp.async.commit_group;" ::: "memory")
#define CP_WAIT1()  asm volatile("cp.async.wait_group 1;" ::: "memory")
#define CP_WAIT0()  asm volatile("cp.async.wait_group 0;" ::: "memory")

// ---------------- elementwise tf32 rounding pass ----------------
__global__ void round_pass_kernel(const float* __restrict__ in, float* __restrict__ out,
                                  int n4)
{
    const int stride = gridDim.x * blockDim.x;
    for (int i = blockIdx.x * blockDim.x + threadIdx.x; i < n4; i += stride) {
        float4 v = ((const float4*)in)[i];
        v.x = round_tf32(v.x); v.y = round_tf32(v.y);
        v.z = round_tf32(v.z); v.w = round_tf32(v.w);
        ((float4*)out)[i] = v;
    }
}

// ---------------- tensor-core tf32 GEMM (mma.sync + cp.async, pre-rounded inputs) ----------------
// All GEMM inputs are ALREADY tf32-rounded (low 13 mantissa bits zero), so fragments
// feed raw bits to mma with no cvt in the hot loop.
// C[m,n] = alpha * sum_k A[m,k] * (TRANSB ? B[n,k] : B[k,n])
// BM=BN=128, BK=64, 256 threads (8 warps: 4m x 2n), warp tile 32x64, 2-stage cp.async.
// SKIPN: skip tiles with n0 > m0+127.  CLAMPK: clamp K to m0+128.
// ROUNDC: round output to tf32 at store.
#define STG_WORDS 8704
#define GEMM_SMEM_BYTES (4 * STG_WORDS * 4)

template <bool TRANSB, bool SKIPN, bool CLAMPK, bool ROUNDC>
__global__ __launch_bounds__(256)
void tmma_gemm(const float* __restrict__ A, const float* __restrict__ B,
               float* __restrict__ C,
               int M, int N, int K, int lda, int ldb, int ldc,
               long long sA, long long sB, long long sC, float alpha)
{
    extern __shared__ float smf[];
    float* Abuf = smf;                   // 2 x 8704
    float* Bbuf = smf + 2 * STG_WORDS;   // 2 x 8704

    const int tid  = threadIdx.x;
    const int wid  = tid >> 5;
    const int lane = tid & 31;
    const int g    = lane >> 2;
    const int tig  = lane & 3;

    const int wm = (wid >> 1) * 32;
    const int wn = (wid & 1) * 64;

    const int z  = blockIdx.z;
    const int m0 = blockIdx.y * 128;
    const int n0 = blockIdx.x * 128;

    if (SKIPN && n0 > m0 + 127) return;

    A += (size_t)z * sA;
    B += (size_t)z * sB;
    C += (size_t)z * sC;

    int Keff = K;
    if (CLAMPK) Keff = min(K, m0 + 128);
    const int nkt = Keff >> 6;

    const uint32_t a_sm = (uint32_t)__cvta_generic_to_shared(Abuf);
    const uint32_t b_sm = (uint32_t)__cvta_generic_to_shared(Bbuf);

    auto load_tile = [&](int kt, int st) {
        const int k0 = kt << 6;
        const uint32_t asb = a_sm + (uint32_t)st * STG_WORDS * 4;
        const uint32_t bsb = b_sm + (uint32_t)st * STG_WORDS * 4;
#pragma unroll
        for (int i = 0; i < 8; i++) {
            const int idx = i * 256 + tid;
            const int row = idx >> 4;
            const int c4  = (idx & 15) * 4;
            const uint32_t dst = asb + (uint32_t)(row * 68 + c4) * 4;
            const float* src = A + (size_t)(m0 + row) * lda + k0 + c4;
            CP_ASYNC16(dst, src, 16);
        }
        if (TRANSB) {
#pragma unroll
            for (int i = 0; i < 8; i++) {
                const int idx = i * 256 + tid;
                const int row = idx >> 4;
                const int c4  = (idx & 15) * 4;
                const bool in = (n0 + row < N);
                const uint32_t dst = bsb + (uint32_t)(row * 68 + c4) * 4;
                const float* src = in ? (B + (size_t)(n0 + row) * ldb + k0 + c4) : B;
                CP_ASYNC16(dst, src, in ? 16 : 0);
            }
        } else {
#pragma unroll
            for (int i = 0; i < 8; i++) {
                const int idx = i * 256 + tid;
                const int row = idx >> 5;
                const int c4  = (idx & 31) * 4;
                const bool in = (n0 + c4 < N);
                const uint32_t dst = bsb + (uint32_t)(row * 136 + c4) * 4;
                const float* src = in ? (B + (size_t)(k0 + row) * ldb + n0 + c4) : B;
                CP_ASYNC16(dst, src, in ? 16 : 0);
            }
        }
    };

    float acc[2][8][4];
#pragma unroll
    for (int mt = 0; mt < 2; mt++)
#pragma unroll
        for (int nt = 0; nt < 8; nt++)
#pragma unroll
            for (int r = 0; r < 4; r++) acc[mt][nt][r] = 0.0f;

    load_tile(0, 0);
    CP_COMMIT();

    for (int kt = 0; kt < nkt; kt++) {
        if (kt + 1 < nkt) {
            load_tile(kt + 1, (kt + 1) & 1);
            CP_COMMIT();
            CP_WAIT1();
        } else {
            CP_WAIT0();
        }
        __syncthreads();

        const uint32_t* Ast = (const uint32_t*)(Abuf + (kt & 1) * STG_WORDS);
        const uint32_t* Bst = (const uint32_t*)(Bbuf + (kt & 1) * STG_WORDS);

#pragma unroll
        for (int ks = 0; ks < 8; ks++) {
            const int kk = ks * 8;
            uint32_t af[2][4];
#pragma unroll
            for (int mt = 0; mt < 2; mt++) {
                const int rb = wm + mt * 16 + g;
                af[mt][0] = Ast[rb * 68 + kk + tig];
                af[mt][1] = Ast[(rb + 8) * 68 + kk + tig];
                af[mt][2] = Ast[rb * 68 + kk + tig + 4];
                af[mt][3] = Ast[(rb + 8) * 68 + kk + tig + 4];
            }
            uint32_t bf[8][2];
#pragma unroll
            for (int nt = 0; nt < 8; nt++) {
                const int nb = wn + nt * 8 + g;
                if (TRANSB) {
                    bf[nt][0] = Bst[nb * 68 + kk + tig];
                    bf[nt][1] = Bst[nb * 68 + kk + tig + 4];
                } else {
                    bf[nt][0] = Bst[(kk + tig) * 136 + nb];
                    bf[nt][1] = Bst[(kk + tig + 4) * 136 + nb];
                }
            }
#pragma unroll
            for (int mt = 0; mt < 2; mt++)
#pragma unroll
                for (int nt = 0; nt < 8; nt++)
                    mma_tf32(acc[mt][nt], af[mt], bf[nt]);
        }
        __syncthreads();
    }

    // ---- epilogue ----
#pragma unroll
    for (int mt = 0; mt < 2; mt++) {
#pragma unroll
        for (int nt = 0; nt < 8; nt++) {
            const int col = n0 + wn + nt * 8 + 2 * tig;
            if (col < N) {
                const int r0 = m0 + wm + mt * 16 + g;
                float o0 = alpha * acc[mt][nt][0], o1 = alpha * acc[mt][nt][1];
                float o2 = alpha * acc[mt][nt][2], o3 = alpha * acc[mt][nt][3];
                if (ROUNDC) {
                    o0 = round_tf32(o0); o1 = round_tf32(o1);
                    o2 = round_tf32(o2); o3 = round_tf32(o3);
                }
                *(float2*)&C[(size_t)r0 * ldc + col]       = make_float2(o0, o1);
                *(float2*)&C[(size_t)(r0 + 8) * ldc + col] = make_float2(o2, o3);
            }
        }
    }
}

// ---------------- rmsnorm (writes tf32-rounded output) ----------------
__global__ void rmsnorm_kernel(float* __restrict__ x, const float* __restrict__ g,
                               int rowstride, int w)
{
    const int row = blockIdx.x;
    float* p = x + (size_t)row * rowstride;
    __shared__ float red[256];
    float s = 0.0f;
    for (int c = threadIdx.x; c < w; c += 256) { float v = p[c]; s += v * v; }
    red[threadIdx.x] = s;
    __syncthreads();
    for (int o = 128; o > 0; o >>= 1) {
        if (threadIdx.x < o) red[threadIdx.x] += red[threadIdx.x + o];
        __syncthreads();
    }
    const float r = rsqrtf(red[0] / (float)w + 1e-6f);
    for (int c = threadIdx.x; c < w; c += 256)
        p[c] = round_tf32(p[c] * r * g[c]);
}

// ---------------- interleaved RoPE (writes rounded; optionally rounds nope part) ----------------
__global__ void rope_kernel(float* __restrict__ base, const int* __restrict__ positions,
                            int rowstride, int headstride, int offset, int round_nope)
{
    const int t = blockIdx.x;
    const int h = blockIdx.y;
    const int i = threadIdx.x;  // 0..31
    float* hp = base + (size_t)t * rowstride + h * headstride;
    float* p = hp + offset;
    const float pos = (float)positions[t];
    const float inv = powf(10000.0f, -(float)(2 * i) / 64.0f);
    float sn, cs;
    sincosf(pos * inv, &sn, &cs);
    const float x1 = p[2 * i];
    const float x2 = p[2 * i + 1];
    p[2 * i]     = round_tf32(x1 * cs - x2 * sn);
    p[2 * i + 1] = round_tf32(x1 * sn + x2 * cs);
    if (round_nope) {
#pragma unroll
        for (int j = 0; j < 4; j++)
            hp[i * 4 + j] = round_tf32(hp[i * 4 + j]);
    }
}

// ---------------- build k_full ----------------
__global__ void kfull_kernel()
{
    const int t = blockIdx.x;
    const int h = blockIdx.y;
    const int d = threadIdx.x;
    float v;
    if (d < DN) v = g_kv[(size_t)t * (NH * (DN + DV)) + h * (DN + DV) + d];
    else        v = g_kva[(size_t)t * (KVL + DR) + KVL + (d - DN)];
    g_kfull[(size_t)t * (NH * DH) + h * DH + d] = v;
}

// ---------------- causal softmax: stores rounded exp, sums unrounded ----------------
__global__ void softmax_kernel(const int* __restrict__ positions)
{
    const int q = blockIdx.x;
    const int h = blockIdx.y;
    float* row = g_s + ((size_t)h * T_TOK + q) * T_TOK;
    const int pq = positions[q];
    const int jmax = ((q >> 7) + 1) << 7;
    __shared__ float red[256];
    const int tid = threadIdx.x;

    float m = -INFINITY;
    for (int j = tid; j < jmax; j += 256)
        if (positions[j] <= pq) m = fmaxf(m, row[j]);
    red[tid] = m;
    __syncthreads();
    for (int o = 128; o > 0; o >>= 1) {
        if (tid < o) red[tid] = fmaxf(red[tid], red[tid + o]);
        __syncthreads();
    }
    m = red[0];
    __syncthreads();

    float s = 0.0f;
    for (int j = tid; j < jmax; j += 256) {
        float v = 0.0f;
        if (positions[j] <= pq) { v = __expf(row[j] - m); s += v; }
        row[j] = round_tf32(v);
    }
    red[tid] = s;
    __syncthreads();
    for (int o = 128; o > 0; o >>= 1) {
        if (tid < o) red[tid] += red[tid + o];
        __syncthreads();
    }
    if (tid == 0) g_rowsum[(size_t)h * T_TOK + q] = red[0];
}

// ---------------- normalize attn rows (writes rounded) ----------------
__global__ void attn_norm_kernel()
{
    const int t = blockIdx.x;
    float* p = g_attn + (size_t)t * (NH * DV);
    for (int c = threadIdx.x; c < NH * DV; c += 256) {
        const int h = c >> 7;
        p[c] = round_tf32(p[c] * (1.0f / g_rowsum[(size_t)h * T_TOK + t]));
    }
}

// ---------------- launcher ----------------
extern "C" void kernel_launch(void* const* d_in, const int* in_sizes, int n_in,
                              void* d_out, int out_size)
{
    const int*   positions = (const int*)  d_in[0];
    const float* hidden    = (const float*)d_in[1];
    const float* wq_a      = (const float*)d_in[2];
    const float* gq        = (const float*)d_in[3];
    const float* wq_b      = (const float*)d_in[4];
    const float* wkv_a     = (const float*)d_in[5];
    const float* gkv       = (const float*)d_in[6];
    const float* wkv_b     = (const float*)d_in[7];
    const float* wo        = (const float*)d_in[8];
    float* out = (float*)d_out;

    float *qa, *q, *kva, *kv, *kfull, *s, *attn;
    float *hidr, *wqa, *wqb, *wkva, *wkvb, *wor;
    cudaGetSymbolAddress((void**)&qa,    g_qa);
    cudaGetSymbolAddress((void**)&q,     g_q);
    cudaGetSymbolAddress((void**)&kva,   g_kva);
    cudaGetSymbolAddress((void**)&kv,    g_kv);
    cudaGetSymbolAddress((void**)&kfull, g_kfull);
    cudaGetSymbolAddress((void**)&s,     g_s);
    cudaGetSymbolAddress((void**)&attn,  g_attn);
    cudaGetSymbolAddress((void**)&hidr,  g_hidr);
    cudaGetSymbolAddress((void**)&wqa,   g_wqa);
    cudaGetSymbolAddress((void**)&wqb,   g_wqb);
    cudaGetSymbolAddress((void**)&wkva,  g_wkva);
    cudaGetSymbolAddress((void**)&wkvb,  g_wkvb);
    cudaGetSymbolAddress((void**)&wor,   g_wo);

    static bool attr_done = false;
    if (!attr_done) {
        cudaFuncSetAttribute(tmma_gemm<false,false,false,false>,
            cudaFuncAttributeMaxDynamicSharedMemorySize, GEMM_SMEM_BYTES);
        cudaFuncSetAttribute(tmma_gemm<false,false,false,true>,
            cudaFuncAttributeMaxDynamicSharedMemorySize, GEMM_SMEM_BYTES);
        cudaFuncSetAttribute(tmma_gemm<true,true,false,false>,
            cudaFuncAttributeMaxDynamicSharedMemorySize, GEMM_SMEM_BYTES);
        cudaFuncSetAttribute(tmma_gemm<false,false,true,false>,
            cudaFuncAttributeMaxDynamicSharedMemorySize, GEMM_SMEM_BYTES);
        attr_done = true;
    }

    const float scale = 1.0f / sqrtf((float)DH);
    const dim3 blk(256);
    const int  shm = GEMM_SMEM_BYTES;

    // 0. pre-round raw inputs to tf32 (idempotent-safe, once per call)
    round_pass_kernel<<<1024, 256>>>(hidden, hidr, (int)((size_t)T_TOK * HID / 4));
    round_pass_kernel<<<1024, 256>>>(wq_a,   wqa,  (int)((size_t)HID * QL / 4));
    round_pass_kernel<<<1024, 256>>>(wq_b,   wqb,  (int)((size_t)QL * NH * DH / 4));
    round_pass_kernel<<<1024, 256>>>(wkv_a,  wkva, (int)((size_t)HID * (KVL + DR) / 4));
    round_pass_kernel<<<1024, 256>>>(wkv_b,  wkvb, (int)((size_t)KVL * NH * (DN + DV) / 4));
    round_pass_kernel<<<1024, 256>>>(wo,     wor,  (int)((size_t)NH * DV * HID / 4));

    // 1. qa = hidr @ wqa             [2048,1536] K=4096  (epilogue fp32; rmsnorm rounds)
    tmma_gemm<false,false,false,false><<<dim3(QL/128, T_TOK/128, 1), blk, shm>>>(
        hidr, wqa, qa, T_TOK, QL, HID, HID, QL, QL, 0, 0, 0, 1.0f);

    // 2. rmsnorm(qa) -> rounded
    rmsnorm_kernel<<<T_TOK, 256>>>(qa, gq, QL, QL);

    // 3. q = qln @ wqb               [2048,6144] K=1536  (rope rounds pe+nope)
    tmma_gemm<false,false,false,false><<<dim3(NH*DH/128, T_TOK/128, 1), blk, shm>>>(
        qa, wqb, q, T_TOK, NH*DH, QL, QL, NH*DH, NH*DH, 0, 0, 0, 1.0f);

    // 4. kva = hidr @ wkva           [2048,576] K=4096
    tmma_gemm<false,false,false,false><<<dim3((KVL+DR+127)/128, T_TOK/128, 1), blk, shm>>>(
        hidr, wkva, kva, T_TOK, KVL+DR, HID, HID, KVL+DR, KVL+DR, 0, 0, 0, 1.0f);

    // 5. rmsnorm first 512 cols of kva -> rounded
    rmsnorm_kernel<<<T_TOK, 256>>>(kva, gkv, KVL+DR, KVL);

    // 6. kv = ckv_ln @ wkvb          [2048,8192] K=512  (epilogue rounds)
    tmma_gemm<false,false,false,true><<<dim3(NH*(DN+DV)/128, T_TOK/128, 1), blk, shm>>>(
        kva, wkvb, kv, T_TOK, NH*(DN+DV), KVL, KVL+DR, NH*(DN+DV), NH*(DN+DV),
        0, 0, 0, 1.0f);

    // 7. rope q_pe (+ round q_nope)
    rope_kernel<<<dim3(T_TOK, NH), 32>>>(q, positions, NH*DH, DH, DN, 1);

    // 8. rope k_pe
    rope_kernel<<<dim3(T_TOK, 1), 32>>>(kva, positions, KVL+DR, 0, KVL, 0);

    // 9. k_full (copies already-rounded values)
    kfull_kernel<<<dim3(T_TOK, NH), DH>>>();

    // 10. scores[h] = scale * q[h] @ kfull[h]^T   (causal tile skip; fp32 out)
    tmma_gemm<true,true,false,false><<<dim3(T_TOK/128, T_TOK/128, NH), blk, shm>>>(
        q, kfull, s, T_TOK, T_TOK, DH, NH*DH, NH*DH, T_TOK,
        (long long)DH, (long long)DH, (long long)T_TOK*T_TOK, scale);

    // 11. causal softmax (stores rounded exp, sums fp32)
    softmax_kernel<<<dim3(T_TOK, NH), 256>>>(positions);

    // 12. attn[h] = exp_probs[h] @ v[h]   (causal K clamp; fp32 out)
    tmma_gemm<false,false,true,false><<<dim3(1, T_TOK/128, NH), blk, shm>>>(
        s, kv + DN, attn, T_TOK, DV, T_TOK, T_TOK, NH*(DN+DV), NH*DV,
        (long long)T_TOK*T_TOK, (long long)(DN+DV), (long long)DV, 1.0f);

    // 12b. normalize attn -> rounded
    attn_norm_kernel<<<T_TOK, 256>>>();

    // 13. out = attn @ wor            [2048,4096]  (final fp32)
    tmma_gemm<false,false,false,false><<<dim3(HID/128, T_TOK/128, 1), blk, shm>>>(
        attn, wor, out, T_TOK, HID, NH*DV, NH*DV, HID, HID, 0, 0, 0, 1.0f);
}